// round 15
// baseline (speedup 1.0000x reference)
#include <cuda_runtime.h>
#include <cuda_fp16.h>
#include <cstdint>

// Problem constants (from reference): B=32, R=256, T=4096, t uniform grid
#define T_LEN 4096
#define THREADS 256
#define ITEMS (T_LEN / THREADS)   // 16: thread owns [tid*16, tid*16+16)
#define QUADS (T_LEN / 4 / THREADS) // 4 q-quads per thread
#define EPS 1e-8f

__global__ void w2_zero_kernel(float* __restrict__ out) { out[0] = 0.0f; }

// Skew (4-byte words): addr(i) = i + (i>>5).
// Gather (i = 16*lane + c): bank bijective in lane -> conflict-free LDS.32.
// Staging (quad 4g..4g+3): addr(4g+r) = 4g + (g>>3) + r, contiguous, CF.
__device__ __forceinline__ int raddr(int i) { return i + (i >> 5); }

__global__ __launch_bounds__(THREADS, 4) void w2_row_kernel(
    const float* __restrict__ traces,
    const float* __restrict__ t,
    const float* __restrict__ q_raw,
    float* __restrict__ out,
    int n_rows)
{
    const int row0 = 2 * blockIdx.x;
    const bool has2 = (row0 + 1) < n_rows;
    const float* __restrict__ x0 = traces + (size_t)row0 * T_LEN;
    const float* __restrict__ q0 = q_raw + (size_t)row0 * T_LEN;
    const float* __restrict__ x1 = x0 + T_LEN;
    const float* __restrict__ q1 = q0 + T_LEN;

    __shared__ __half2 sh_r[T_LEN + T_LEN / 32];  // residual pair table (~16.9 KB)
    __shared__ float sh_last[8];
    __shared__ float sh_wsum[8];
    __shared__ float sh_woff[9];
    __shared__ float sh_red[8];

    const int tid  = threadIdx.x;
    const int lane = tid & 31;
    const int w    = tid >> 5;
    const int base = tid * ITEMS;

    const float t0 = __ldg(t);
    const float dt = __ldg(t + 1) - t0;

    float acc_total = 0.0f;

    // ===================== ROW 0: load =====================
    float s0[ITEMS];
    float4 qv0[QUADS];
    {
        const float4* x4 = reinterpret_cast<const float4*>(x0 + base);
        const float4* q4 = reinterpret_cast<const float4*>(q0);
#pragma unroll
        for (int k = 0; k < QUADS; k++) qv0[k] = q4[tid + k * THREADS];
#pragma unroll
        for (int k = 0; k < ITEMS / 4; k++) {
            float4 v = x4[k];
            s0[4 * k + 0] = v.x * v.x + EPS;
            s0[4 * k + 1] = v.y * v.y + EPS;
            s0[4 * k + 2] = v.z * v.z + EPS;
            s0[4 * k + 3] = v.w * v.w + EPS;
        }
    }
    // stage row-0 residual table
#pragma unroll
    for (int k = 0; k < QUADS; k++) {
        int g = tid + k * THREADS;
        float4 v = qv0[k];
        float nx = __shfl_down_sync(0xffffffffu, v.x, 1);
        if (lane == 31)
            nx = (g == T_LEN / 4 - 1) ? v.w : __ldg(q0 + 4 * g + 4);
        float tg = fmaf((float)(4 * g), dt, t0);
        float r0 = v.x - tg;
        float r1 = v.y - (tg + dt);
        float r2 = v.z - (tg + 2.0f * dt);
        float r3 = v.w - (tg + 3.0f * dt);
        float r4 = nx  - (tg + 4.0f * dt);
        int a = 4 * g + (g >> 3);
        sh_r[a + 0] = __floats2half2_rn(r0, r1);
        sh_r[a + 1] = __floats2half2_rn(r1, r2);
        sh_r[a + 2] = __floats2half2_rn(r2, r3);
        sh_r[a + 3] = __floats2half2_rn(r3, r4);
    }
    if (lane == 31) sh_last[w] = s0[ITEMS - 1];
    __syncthreads();

    // row-0 scan
    float prev_s0 = __shfl_up_sync(0xffffffffu, s0[ITEMS - 1], 1);
    if (lane == 0) prev_s0 = (w > 0) ? sh_last[w - 1] : -s0[0];
    float run0;
    {
        float a0 = s0[0]  + s0[1],  a1 = s0[2]  + s0[3];
        float a2 = s0[4]  + s0[5],  a3 = s0[6]  + s0[7];
        float a4 = s0[8]  + s0[9],  a5 = s0[10] + s0[11];
        float a6 = s0[12] + s0[13], a7 = s0[14] + s0[15];
        float tot = ((a0 + a1) + (a2 + a3)) + ((a4 + a5) + (a6 + a7));
        run0 = fmaf(0.5f, prev_s0 - s0[ITEMS - 1], tot);
    }
    float v0 = run0;
#pragma unroll
    for (int o = 1; o < 32; o <<= 1) {
        float u = __shfl_up_sync(0xffffffffu, v0, o);
        if (lane >= o) v0 += u;
    }
    if (lane == 31) sh_wsum[w] = v0;
    __syncthreads();
    if (tid == 0) {
        float a = 0.0f;
#pragma unroll
        for (int i = 0; i < 8; i++) { sh_woff[i] = a; a += sh_wsum[i]; }
        sh_woff[8] = a;
    }
    __syncthreads();
    const float invU0   = __fdividef(1.0f, sh_woff[8]);
    const float scale0  = invU0 * (float)(T_LEN - 1);
    const float cs0     = 0.5f * scale0;
    const float offset0 = sh_woff[w] + (v0 - run0);

    // ===================== ROW 1: issue loads NOW (hide under loss-0) =====================
    float s1[ITEMS];
    float4 qv1[QUADS];
    if (has2) {
        const float4* x4 = reinterpret_cast<const float4*>(x1 + base);
        const float4* q4 = reinterpret_cast<const float4*>(q1);
#pragma unroll
        for (int k = 0; k < QUADS; k++) qv1[k] = q4[tid + k * THREADS];
#pragma unroll
        for (int k = 0; k < ITEMS / 4; k++) {
            float4 v = x4[k];
            s1[4 * k + 0] = v.x * v.x + EPS;
            s1[4 * k + 1] = v.y * v.y + EPS;
            s1[4 * k + 2] = v.z * v.z + EPS;
            s1[4 * k + 3] = v.w * v.w + EPS;
        }
    }

    // ===================== ROW 0: loss =====================
    {
        float acc = 0.0f;
        float d_first = 0.0f, d_last = 0.0f;
        float p   = prev_s0;
        float pos = offset0 * scale0;
        float jf  = (float)base;
#pragma unroll
        for (int k = 0; k < ITEMS; k++) {
            pos = fmaf(cs0, p + s0[k], pos);
            p = s0[k];
            int   i  = (int)pos;
            float fr = pos - (float)i;
            float2 rf = __half22float2(sh_r[raddr(i)]);
            float rint = fmaf(fr, rf.y - rf.x, rf.x);
            float d = fmaf(dt, jf - pos, -rint);
            if (k == 0)         d_first = d;
            if (k == ITEMS - 1) d_last  = d;
            acc = fmaf(d * d, s0[k], acc);
            jf += 1.0f;
        }
        if (tid == 0)           acc -= 0.5f * d_first * d_first * s0[0];
        if (tid == THREADS - 1) acc -= 0.5f * d_last  * d_last  * s0[ITEMS - 1];
        acc_total += acc * invU0;
    }
    __syncthreads();   // all gathers on row-0 table done

    // ===================== ROW 1: stage + scan + loss =====================
    if (has2) {
#pragma unroll
        for (int k = 0; k < QUADS; k++) {
            int g = tid + k * THREADS;
            float4 v = qv1[k];
            float nx = __shfl_down_sync(0xffffffffu, v.x, 1);
            if (lane == 31)
                nx = (g == T_LEN / 4 - 1) ? v.w : __ldg(q1 + 4 * g + 4);
            float tg = fmaf((float)(4 * g), dt, t0);
            float r0 = v.x - tg;
            float r1 = v.y - (tg + dt);
            float r2 = v.z - (tg + 2.0f * dt);
            float r3 = v.w - (tg + 3.0f * dt);
            float r4 = nx  - (tg + 4.0f * dt);
            int a = 4 * g + (g >> 3);
            sh_r[a + 0] = __floats2half2_rn(r0, r1);
            sh_r[a + 1] = __floats2half2_rn(r1, r2);
            sh_r[a + 2] = __floats2half2_rn(r2, r3);
            sh_r[a + 3] = __floats2half2_rn(r3, r4);
        }
        if (lane == 31) sh_last[w] = s1[ITEMS - 1];
        __syncthreads();

        float prev_s1 = __shfl_up_sync(0xffffffffu, s1[ITEMS - 1], 1);
        if (lane == 0) prev_s1 = (w > 0) ? sh_last[w - 1] : -s1[0];
        float run1;
        {
            float a0 = s1[0]  + s1[1],  a1 = s1[2]  + s1[3];
            float a2 = s1[4]  + s1[5],  a3 = s1[6]  + s1[7];
            float a4 = s1[8]  + s1[9],  a5 = s1[10] + s1[11];
            float a6 = s1[12] + s1[13], a7 = s1[14] + s1[15];
            float tot = ((a0 + a1) + (a2 + a3)) + ((a4 + a5) + (a6 + a7));
            run1 = fmaf(0.5f, prev_s1 - s1[ITEMS - 1], tot);
        }
        float v1 = run1;
#pragma unroll
        for (int o = 1; o < 32; o <<= 1) {
            float u = __shfl_up_sync(0xffffffffu, v1, o);
            if (lane >= o) v1 += u;
        }
        if (lane == 31) sh_wsum[w] = v1;
        __syncthreads();
        if (tid == 0) {
            float a = 0.0f;
#pragma unroll
            for (int i = 0; i < 8; i++) { sh_woff[i] = a; a += sh_wsum[i]; }
            sh_woff[8] = a;
        }
        __syncthreads();
        const float invU1   = __fdividef(1.0f, sh_woff[8]);
        const float scale1  = invU1 * (float)(T_LEN - 1);
        const float cs1     = 0.5f * scale1;
        const float offset1 = sh_woff[w] + (v1 - run1);

        float acc = 0.0f;
        float d_first = 0.0f, d_last = 0.0f;
        float p   = prev_s1;
        float pos = offset1 * scale1;
        float jf  = (float)base;
#pragma unroll
        for (int k = 0; k < ITEMS; k++) {
            pos = fmaf(cs1, p + s1[k], pos);
            p = s1[k];
            int   i  = (int)pos;
            float fr = pos - (float)i;
            float2 rf = __half22float2(sh_r[raddr(i)]);
            float rint = fmaf(fr, rf.y - rf.x, rf.x);
            float d = fmaf(dt, jf - pos, -rint);
            if (k == 0)         d_first = d;
            if (k == ITEMS - 1) d_last  = d;
            acc = fmaf(d * d, s1[k], acc);
            jf += 1.0f;
        }
        if (tid == 0)           acc -= 0.5f * d_first * d_first * s1[0];
        if (tid == THREADS - 1) acc -= 0.5f * d_last  * d_last  * s1[ITEMS - 1];
        acc_total += acc * invU1;
    }

    // ---- block reduce + global atomic (one per CTA, two rows) ----
#pragma unroll
    for (int o = 16; o > 0; o >>= 1)
        acc_total += __shfl_xor_sync(0xffffffffu, acc_total, o);
    if (lane == 0) sh_red[w] = acc_total;
    __syncthreads();
    if (tid == 0) {
        float ssum = 0.0f;
#pragma unroll
        for (int i = 0; i < 8; i++) ssum += sh_red[i];
        atomicAdd(out, ssum);
    }
}

extern "C" void kernel_launch(void* const* d_in, const int* in_sizes, int n_in,
                              void* d_out, int out_size)
{
    // Inputs (metadata order): traces [B*R*T], t [T], p [T] (uniform [0,1], unused),
    // q_raw [B*R*T]. Output: scalar float loss.
    const float* traces = (const float*)d_in[0];
    const float* t      = (const float*)d_in[1];
    const float* q_raw  = (const float*)d_in[3];
    float* out = (float*)d_out;

    int n_rows = in_sizes[0] / T_LEN;
    int n_cta  = (n_rows + 1) / 2;

    w2_zero_kernel<<<1, 1>>>(out);
    w2_row_kernel<<<n_cta, THREADS>>>(traces, t, q_raw, out, n_rows);
}

// round 16
// speedup vs baseline: 1.1607x; 1.1607x over previous
#include <cuda_runtime.h>
#include <cuda_fp16.h>
#include <cstdint>

// Problem constants (from reference): B=32, R=256, T=4096, t uniform grid
#define T_LEN 4096
#define THREADS 256
#define ITEMS (T_LEN / THREADS)   // 16: thread owns [tid*16, tid*16+16)
#define EPS 1e-8f

__global__ void w2_zero_kernel(float* __restrict__ out) { out[0] = 0.0f; }

// Skew (4-byte words): addr(i) = i + (i>>5).
// Gather (i = 16*lane + c): bank bijective in lane -> conflict-free LDS.32.
// Staging (quad 4g..4g+3): addr(4g+r) = 4g + (g>>3) + r, contiguous, CF.
__device__ __forceinline__ int raddr(int i) { return i + (i >> 5); }

__global__ __launch_bounds__(THREADS, 6) void w2_row_kernel(
    const float* __restrict__ traces,
    const float* __restrict__ t,
    const float* __restrict__ q_raw,
    float* __restrict__ out)
{
    const int row = blockIdx.x;
    const float* __restrict__ x = traces + (size_t)row * T_LEN;
    const float* __restrict__ q = q_raw + (size_t)row * T_LEN;

    __shared__ __half2 sh_r[T_LEN + T_LEN / 32];  // residual pair table (~16.9 KB)
    __shared__ float sh_last[8];           // lane-31 thread's s[15] per warp
    __shared__ float sh_wsum[8];           // per-warp totals
    __shared__ float sh_woff[9];           // exclusive warp offsets; [8] = U total
    __shared__ float sh_red[8];

    const int tid  = threadIdx.x;
    const int lane = tid & 31;
    const int w    = tid >> 5;
    const int base = tid * ITEMS;

    // ---- grid params (uniform t) ----
    const float t0 = __ldg(t);
    const float dt = __ldg(t + 1) - t0;

    // ---- stage residual pair table: r[i] = q[i] - (t0 + i*dt), half2(r_i, r_{i+1}) ----
    {
        const float4* q4 = reinterpret_cast<const float4*>(q);
#pragma unroll
        for (int k = 0; k < T_LEN / 4 / THREADS; k++) {
            int g = tid + k * THREADS;          // float4 index
            float4 v = q4[g];
            // q[4g+4]: lane+1's v.x; lane 31 crosses warps -> L1-hit ldg
            float nx = __shfl_down_sync(0xffffffffu, v.x, 1);
            if (lane == 31)
                nx = (g == T_LEN / 4 - 1) ? v.w : __ldg(q + 4 * g + 4);
            float tg = fmaf((float)(4 * g), dt, t0);
            float r0 = v.x - tg;
            float r1 = v.y - (tg + dt);
            float r2 = v.z - (tg + 2.0f * dt);
            float r3 = v.w - (tg + 3.0f * dt);
            float r4 = nx  - (tg + 4.0f * dt);
            int a = 4 * g + (g >> 3);           // raddr(4g); quad contiguous
            sh_r[a + 0] = __floats2half2_rn(r0, r1);
            sh_r[a + 1] = __floats2half2_rn(r1, r2);
            sh_r[a + 2] = __floats2half2_rn(r2, r3);
            sh_r[a + 3] = __floats2half2_rn(r3, r4);
        }
    }

    // ---- load x (blocked, float4), square+eps into registers ----
    float s[ITEMS];
    {
        const float4* x4 = reinterpret_cast<const float4*>(x + base);
#pragma unroll
        for (int k = 0; k < ITEMS / 4; k++) {
            float4 v = x4[k];
            s[4 * k + 0] = v.x * v.x + EPS;
            s[4 * k + 1] = v.y * v.y + EPS;
            s[4 * k + 2] = v.z * v.z + EPS;
            s[4 * k + 3] = v.w * v.w + EPS;
        }
    }

    if (lane == 31) sh_last[w] = s[ITEMS - 1];
    __syncthreads();

    // prev_s = s[base-1]; thread 0 seeds -s[0] so that inc_0 = 0 branch-free
    float prev_s = __shfl_up_sync(0xffffffffu, s[ITEMS - 1], 1);
    if (lane == 0) prev_s = (w > 0) ? sh_last[w - 1] : -s[0];

    // ---- thread total via pairwise tree (no serial chain) ----
    // run = sum_k 0.5*(s[k-1]+s[k]) = sum(s) + 0.5*(prev_s - s[15])
    float run;
    {
        float a0 = s[0]  + s[1],  a1 = s[2]  + s[3];
        float a2 = s[4]  + s[5],  a3 = s[6]  + s[7];
        float a4 = s[8]  + s[9],  a5 = s[10] + s[11];
        float a6 = s[12] + s[13], a7 = s[14] + s[15];
        float b0 = a0 + a1, b1 = a2 + a3, b2 = a4 + a5, b3 = a6 + a7;
        float tot = (b0 + b1) + (b2 + b3);
        run = fmaf(0.5f, prev_s - s[ITEMS - 1], tot);
    }

    // ---- block scan of per-thread totals ----
    float v = run;
#pragma unroll
    for (int o = 1; o < 32; o <<= 1) {
        float u = __shfl_up_sync(0xffffffffu, v, o);
        if (lane >= o) v += u;
    }
    if (lane == 31) sh_wsum[w] = v;
    __syncthreads();
    if (tid == 0) {
        float acc = 0.0f;
#pragma unroll
        for (int i = 0; i < 8; i++) { sh_woff[i] = acc; acc += sh_wsum[i]; }
        sh_woff[8] = acc;                    // U = total (dt-free integral)
    }
    __syncthreads();

    const float U      = sh_woff[8];
    const float invU   = __fdividef(1.0f, U);
    const float scale  = invU * (float)(T_LEN - 1);
    const float cs     = 0.5f * scale;
    const float offset = sh_woff[w] + (v - run);   // exclusive prefix for this thread

    // ---- loss: track pos directly, single-LDS residual gather ----
    float acc = 0.0f;
    float d_first = 0.0f, d_last = 0.0f;
    {
        float p   = prev_s;
        float pos = offset * scale;
        float jf  = (float)base;             // exact integers up to 4095
#pragma unroll
        for (int k = 0; k < ITEMS; k++) {
            pos = fmaf(cs, p + s[k], pos);   // pos = cdf * 4095, in [0, 4095]
            p = s[k];

            int   i  = (int)pos;             // 0..4095; entry 4095 is valid
            float fr = pos - (float)i;
            float2 rf = __half22float2(sh_r[raddr(i)]);
            float rint = fmaf(fr, rf.y - rf.x, rf.x);

            // d = (t0 + j*dt) - transport = dt*(j - pos) - rint
            float d = fmaf(dt, jf - pos, -rint);
            if (k == 0)         d_first = d;
            if (k == ITEMS - 1) d_last  = d;
            acc = fmaf(d * d, s[k], acc);
            jf += 1.0f;
        }
    }
    // trapz end-point half weights (only j=0 and j=T-1)
    if (tid == 0)           acc -= 0.5f * d_first * d_first * s[0];
    if (tid == THREADS - 1) acc -= 0.5f * d_last  * d_last  * s[ITEMS - 1];
    acc *= invU;   // wt*pdf = s_j/U (dt cancels)

    // ---- block reduce + global atomic ----
#pragma unroll
    for (int o = 16; o > 0; o >>= 1)
        acc += __shfl_xor_sync(0xffffffffu, acc, o);
    if (lane == 0) sh_red[w] = acc;
    __syncthreads();
    if (tid == 0) {
        float ssum = 0.0f;
#pragma unroll
        for (int i = 0; i < 8; i++) ssum += sh_red[i];
        atomicAdd(out, ssum);
    }
}

extern "C" void kernel_launch(void* const* d_in, const int* in_sizes, int n_in,
                              void* d_out, int out_size)
{
    // Inputs (metadata order): traces [B*R*T], t [T], p [T] (uniform [0,1], unused),
    // q_raw [B*R*T]. Output: scalar float loss.
    const float* traces = (const float*)d_in[0];
    const float* t      = (const float*)d_in[1];
    const float* q_raw  = (const float*)d_in[3];
    float* out = (float*)d_out;

    int n_rows = in_sizes[0] / T_LEN;

    w2_zero_kernel<<<1, 1>>>(out);
    w2_row_kernel<<<n_rows, THREADS>>>(traces, t, q_raw, out);
}